// round 6
// baseline (speedup 1.0000x reference)
#include <cuda_runtime.h>

#define NCTAS     64
#define NTHREADS  256
#define DIM       1024
#define NGATES    8
#define MAX_TERMS 32

// dynamic smem: 2 G buffers (2*16*DIM) + staged vector (2*DIM) + local psi acc (2*DIM)
#define SMEM_BYTES ((2 * 16 * DIM + 2 * DIM + 2 * DIM) * 4)   // 144 KB

// -------- persistent device scratch (no allocation allowed) --------
__device__ __align__(16) float g_vec[2][2 * DIM];  // ping-pong [re(1024)|im(1024)]
__device__ unsigned g_flags[NCTAS];   // per-CTA monotonic exchange counters
__device__ unsigned g_base;           // epoch base; advanced once per launch by cta0

// -------- PTX helpers --------
static __device__ __forceinline__ unsigned smem_u32(const void* p) {
    return (unsigned)__cvta_generic_to_shared(p);
}
static __device__ __forceinline__ void mbar_init(unsigned mb, unsigned count) {
    asm volatile("mbarrier.init.shared.b64 [%0], %1;" :: "r"(mb), "r"(count) : "memory");
}
static __device__ __forceinline__ void mbar_expect_tx(unsigned mb, unsigned bytes) {
    asm volatile("mbarrier.arrive.expect_tx.shared.b64 _, [%0], %1;"
                 :: "r"(mb), "r"(bytes) : "memory");
}
static __device__ __forceinline__ void bulk_g2s(unsigned dst, const void* src,
                                                unsigned bytes, unsigned mb) {
    asm volatile("cp.async.bulk.shared::cluster.global.mbarrier::complete_tx::bytes "
                 "[%0], [%1], %2, [%3];"
                 :: "r"(dst), "l"(src), "r"(bytes), "r"(mb) : "memory");
}
static __device__ __forceinline__ void mbar_wait(unsigned mb, unsigned parity) {
    asm volatile(
        "{\n\t"
        ".reg .pred P1;\n\t"
        "WAIT_LOOP_%=:\n\t"
        "mbarrier.try_wait.parity.shared.b64 P1, [%0], %1, 0x989680;\n\t"
        "@P1 bra.uni WAIT_DONE_%=;\n\t"
        "bra.uni WAIT_LOOP_%=;\n\t"
        "WAIT_DONE_%=:\n\t"
        "}"
        :: "r"(mb), "r"(parity) : "memory");
}
static __device__ __forceinline__ unsigned ld_acquire(const unsigned* p) {
    unsigned v;
    asm volatile("ld.acquire.gpu.u32 %0, [%1];" : "=r"(v) : "l"(p) : "memory");
    return v;
}
static __device__ __forceinline__ void st_release(unsigned* p, unsigned v) {
    asm volatile("st.release.gpu.u32 [%0], %1;" :: "l"(p), "r"(v) : "memory");
}
static __device__ __forceinline__ void stg_cg_f2(float* p, float x, float y) {
    asm volatile("st.global.cg.v2.f32 [%0], {%1, %2};" :: "l"(p), "f"(x), "f"(y) : "memory");
}

__global__ void __launch_bounds__(NTHREADS, 1)
qnn_kernel(const float* __restrict__ feature,
           const float* __restrict__ theta,
           const float* __restrict__ gens,
           float* __restrict__ out)
{
    extern __shared__ __align__(16) float dyn[];
    float* sG   = dyn;                    // [2][16][DIM]
    float* sv   = dyn + 2 * 16 * DIM;     // staged w_n  [re|im]
    float* sacc = sv + 2 * DIM;           // local full psi accumulator [re|im]

    __shared__ unsigned long long mbarG0, mbarG1;
    __shared__ float sred[8];

    const int tid  = threadIdx.x;
    const int cta  = blockIdx.x;
    const int warp = tid >> 5;
    const int lane = tid & 31;
    const int row0 = cta * 16;
    const int la   = 2 * warp;            // this warp's two local rows
    const int r_a  = row0 + la;
    const int r_b  = r_a + 1;

    const unsigned mbG0 = smem_u32(&mbarG0);
    const unsigned mbG1 = smem_u32(&mbarG1);
    const unsigned sG_a = smem_u32(sG);

    const unsigned base = ld_acquire(&g_base);   // written only at end of prior launch
    unsigned it = 0;

    if (tid == 0) {
        mbar_init(mbG0, 1);
        mbar_init(mbG1, 1);
        mbar_expect_tx(mbG0, 65536u);            // G0 load overlaps the norm phase
        bulk_g2s(sG_a, gens + (size_t)row0 * DIM, 65536u, mbG0);
    }
    __syncthreads();

    // ---------- L2 norm of feature; build local psi in sacc (no exchange) ----------
    float ss = 0.f;
    for (int i = tid; i < DIM; i += NTHREADS) { float f = __ldg(&feature[i]); ss += f * f; }
    #pragma unroll
    for (int o = 16; o; o >>= 1) ss += __shfl_xor_sync(~0u, ss, o);
    if (lane == 0) sred[warp] = ss;
    __syncthreads();
    if (warp == 0) {
        float v = (lane < 8) ? sred[lane] : 0.f;
        #pragma unroll
        for (int o = 4; o; o >>= 1) v += __shfl_xor_sync(~0u, v, o);
        if (lane == 0) sred[0] = v;
    }
    __syncthreads();
    const float inv_norm = rsqrtf(sred[0]);
    for (int i = tid; i < DIM; i += NTHREADS) {
        sacc[i]       = __ldg(&feature[i]) * inv_norm;
        sacc[DIM + i] = 0.f;
    }
    __syncthreads();

    int slot = 0;
    int pGb[2] = {0, 0};

    for (int g = 0; g < NGATES; g++) {
        const float t = __ldg(&theta[g]);

        // adaptive Taylor term count (identical arithmetic on every CTA)
        const float z = 1.5f * fabsf(t) + 0.05f;
        int nterms;
        {
            float term = 1.f; int n = 0;
            while (n < MAX_TERMS) { n++; term *= z / (float)n; if (term < 1e-6f) break; }
            nterms = n;
        }

        // prefetch next gate's G tile into the other buffer
        if (tid == 0 && g + 1 < NGATES) {
            const int b = (g + 1) & 1;
            mbar_expect_tx(b ? mbG1 : mbG0, 65536u);
            bulk_g2s(sG_a + (unsigned)b * 65536u,
                     gens + (size_t)(g + 1) * DIM * DIM + (size_t)row0 * DIM,
                     65536u, b ? mbG1 : mbG0);
        }
        // wait for this gate's G tile
        {
            const int b = g & 1;
            mbar_wait(b ? mbG1 : mbG0, pGb[b]);
            pGb[b] ^= 1;
        }

        const float4* A4 = (const float4*)(sG + (size_t)(g & 1) * 16 * DIM + (size_t)la * DIM);
        const float4* B4 = A4 + DIM / 4;

        for (int n = 1; n <= nterms; n++) {
            // term 1 reads psi from sacc; later terms read staged w from sv
            const float4* vr = (n == 1) ? (const float4*)sacc : (const float4*)sv;
            const float4* vi = vr + DIM / 4;

            float dre_a = 0.f, dim_a = 0.f, dre_b = 0.f, dim_b = 0.f;
            #pragma unroll
            for (int k = 0; k < 8; k++) {
                const int idx = lane + 32 * k;
                const float4 va = vr[idx];
                const float4 vb = vi[idx];
                const float4 ga = A4[idx];
                const float4 gb = B4[idx];
                dre_a += ga.x*va.x + ga.y*va.y + ga.z*va.z + ga.w*va.w;
                dim_a += ga.x*vb.x + ga.y*vb.y + ga.z*vb.z + ga.w*vb.w;
                dre_b += gb.x*va.x + gb.y*va.y + gb.z*va.z + gb.w*va.w;
                dim_b += gb.x*vb.x + gb.y*vb.y + gb.z*vb.z + gb.w*vb.w;
            }
            #pragma unroll
            for (int o = 16; o; o >>= 1) {
                dre_a += __shfl_xor_sync(~0u, dre_a, o);
                dim_a += __shfl_xor_sync(~0u, dim_a, o);
                dre_b += __shfl_xor_sync(~0u, dre_b, o);
                dim_b += __shfl_xor_sync(~0u, dim_b, o);
            }
            const float sc = t / (float)n;   // w_n = (-i t/n)(G w_{n-1}): (-i)(a+bi)=b-ai

            if (g == NGATES - 1 && n == nterms) {
                // final term of final gate: everything needed is local — no exchange
                if (lane == 0) {
                    const float fre_a = sacc[r_a]       + sc * dim_a;
                    const float fim_a = sacc[DIM + r_a] - sc * dre_a;
                    const float fre_b = sacc[r_b]       + sc * dim_b;
                    const float fim_b = sacc[DIM + r_b] - sc * dre_b;
                    out[r_a] = fre_a * fre_a + fim_a * fim_a;
                    out[r_b] = fre_b * fre_b + fim_b * fim_b;
                }
                break;
            }

            // ---- dataflow exchange ----
            if (lane == 0) {
                stg_cg_f2(&g_vec[slot][r_a],       sc * dim_a, sc * dim_b);
                stg_cg_f2(&g_vec[slot][DIM + r_a], -sc * dre_a, -sc * dre_b);
                __threadfence();                    // data visible before my flag
            }
            __syncthreads();
            it++;
            const unsigned target = base + it;
            if (tid == 0) st_release(&g_flags[cta], target);
            if (warp == 0) {
                const unsigned* f0 = &g_flags[lane];
                const unsigned* f1 = &g_flags[lane + 32];
                bool ok;
                do {
                    ok = ((int)(ld_acquire(f0) - target) >= 0) &
                         ((int)(ld_acquire(f1) - target) >= 0);
                } while (!__all_sync(~0u, ok));
            }
            __syncthreads();

            // cooperative gather (L2) fused with psi accumulation
            const float4* gv = (const float4*)g_vec[slot];
            #pragma unroll
            for (int j = 0; j < 2; j++) {
                const int idx = tid + j * NTHREADS;
                const float4 w = __ldcg(&gv[idx]);
                ((float4*)sv)[idx] = w;
                float4 a = ((const float4*)sacc)[idx];
                a.x += w.x; a.y += w.y; a.z += w.z; a.w += w.w;
                ((float4*)sacc)[idx] = a;
            }
            __syncthreads();

            slot ^= 1;
        }
    }

    // advance epoch for the next launch/replay (single writer; safe: cta0 reaches
    // here only after every CTA published its final flag)
    if (cta == 0 && tid == 0) st_release(&g_base, base + it);
}

extern "C" void kernel_launch(void* const* d_in, const int* in_sizes, int n_in,
                              void* d_out, int out_size) {
    const float* feature = nullptr;
    const float* theta   = nullptr;
    const float* gens    = nullptr;
    for (int i = 0; i < n_in; i++) {
        if (in_sizes[i] == DIM)                     feature = (const float*)d_in[i];
        else if (in_sizes[i] == NGATES)             theta   = (const float*)d_in[i];
        else if (in_sizes[i] == NGATES * DIM * DIM) gens    = (const float*)d_in[i];
    }
    cudaFuncSetAttribute(qnn_kernel, cudaFuncAttributeMaxDynamicSharedMemorySize, SMEM_BYTES);
    qnn_kernel<<<NCTAS, NTHREADS, SMEM_BYTES>>>(feature, theta, gens, (float*)d_out);
}

// round 7
// speedup vs baseline: 2.1821x; 2.1821x over previous
#include <cuda_runtime.h>

#define NCTAS     64
#define NTHREADS  256
#define DIM       1024
#define NGATES    8
#define MAX_TERMS 32

// dynamic smem: 2 G buffers (2*16*DIM) + staged vector (2*DIM) + local psi acc (2*DIM)
#define SMEM_BYTES ((2 * 16 * DIM + 2 * DIM + 2 * DIM) * 4)   // 144 KB

// -------- persistent device scratch (no allocation allowed) --------
__device__ __align__(16) float g_vec[2][2 * DIM];  // ping-pong [re(1024)|im(1024)]
__device__ unsigned g_cnt;    // monotonic arrival counter (never reset)
__device__ unsigned g_base;   // epoch base; advanced once per launch by cta0

// -------- PTX helpers --------
static __device__ __forceinline__ unsigned smem_u32(const void* p) {
    return (unsigned)__cvta_generic_to_shared(p);
}
static __device__ __forceinline__ void mbar_init(unsigned mb, unsigned count) {
    asm volatile("mbarrier.init.shared.b64 [%0], %1;" :: "r"(mb), "r"(count) : "memory");
}
static __device__ __forceinline__ void mbar_expect_tx(unsigned mb, unsigned bytes) {
    asm volatile("mbarrier.arrive.expect_tx.shared.b64 _, [%0], %1;"
                 :: "r"(mb), "r"(bytes) : "memory");
}
static __device__ __forceinline__ void bulk_g2s(unsigned dst, const void* src,
                                                unsigned bytes, unsigned mb) {
    asm volatile("cp.async.bulk.shared::cluster.global.mbarrier::complete_tx::bytes "
                 "[%0], [%1], %2, [%3];"
                 :: "r"(dst), "l"(src), "r"(bytes), "r"(mb) : "memory");
}
static __device__ __forceinline__ void mbar_wait(unsigned mb, unsigned parity) {
    asm volatile(
        "{\n\t"
        ".reg .pred P1;\n\t"
        "WAIT_LOOP_%=:\n\t"
        "mbarrier.try_wait.parity.shared.b64 P1, [%0], %1, 0x989680;\n\t"
        "@P1 bra.uni WAIT_DONE_%=;\n\t"
        "bra.uni WAIT_LOOP_%=;\n\t"
        "WAIT_DONE_%=:\n\t"
        "}"
        :: "r"(mb), "r"(parity) : "memory");
}
static __device__ __forceinline__ void red_add_release(unsigned* p, unsigned v) {
    asm volatile("red.release.gpu.add.u32 [%0], %1;" :: "l"(p), "r"(v) : "memory");
}
static __device__ __forceinline__ unsigned ld_acquire(const unsigned* p) {
    unsigned v;
    asm volatile("ld.acquire.gpu.u32 %0, [%1];" : "=r"(v) : "l"(p) : "memory");
    return v;
}
static __device__ __forceinline__ void st_release(unsigned* p, unsigned v) {
    asm volatile("st.release.gpu.u32 [%0], %1;" :: "l"(p), "r"(v) : "memory");
}
static __device__ __forceinline__ void stg_cg_f2(float* p, float x, float y) {
    asm volatile("st.global.cg.v2.f32 [%0], {%1, %2};" :: "l"(p), "f"(x), "f"(y) : "memory");
}

__global__ void __launch_bounds__(NTHREADS, 1)
qnn_kernel(const float* __restrict__ feature,
           const float* __restrict__ theta,
           const float* __restrict__ gens,
           float* __restrict__ out)
{
    extern __shared__ __align__(16) float dyn[];
    float* sG   = dyn;                    // [2][16][DIM]
    float* sv   = dyn + 2 * 16 * DIM;     // staged w_n  [re|im]
    float* sacc = sv + 2 * DIM;           // local full psi accumulator [re|im]

    __shared__ unsigned long long mbarG0, mbarG1;
    __shared__ float sred[8];

    const int tid  = threadIdx.x;
    const int cta  = blockIdx.x;
    const int warp = tid >> 5;
    const int lane = tid & 31;
    const int row0 = cta * 16;
    const int la   = 2 * warp;            // this warp's two local rows
    const int r_a  = row0 + la;
    const int r_b  = r_a + 1;

    const unsigned mbG0 = smem_u32(&mbarG0);
    const unsigned mbG1 = smem_u32(&mbarG1);
    const unsigned sG_a = smem_u32(sG);

    const unsigned base = ld_acquire(&g_base);   // written only at end of prior launch
    unsigned it = 0;

    if (tid == 0) {
        mbar_init(mbG0, 1);
        mbar_init(mbG1, 1);
        mbar_expect_tx(mbG0, 65536u);            // G0 load overlaps the norm phase
        bulk_g2s(sG_a, gens + (size_t)row0 * DIM, 65536u, mbG0);
    }
    __syncthreads();

    // ---------- L2 norm of feature; build local psi in sacc (no exchange) ----------
    float ss = 0.f;
    for (int i = tid; i < DIM; i += NTHREADS) { float f = __ldg(&feature[i]); ss += f * f; }
    #pragma unroll
    for (int o = 16; o; o >>= 1) ss += __shfl_xor_sync(~0u, ss, o);
    if (lane == 0) sred[warp] = ss;
    __syncthreads();
    if (warp == 0) {
        float v = (lane < 8) ? sred[lane] : 0.f;
        #pragma unroll
        for (int o = 4; o; o >>= 1) v += __shfl_xor_sync(~0u, v, o);
        if (lane == 0) sred[0] = v;
    }
    __syncthreads();
    const float inv_norm = rsqrtf(sred[0]);
    for (int i = tid; i < DIM; i += NTHREADS) {
        sacc[i]       = __ldg(&feature[i]) * inv_norm;
        sacc[DIM + i] = 0.f;
    }
    __syncthreads();

    int slot = 0;
    int pGb[2] = {0, 0};

    for (int g = 0; g < NGATES; g++) {
        const float t = __ldg(&theta[g]);

        // adaptive Taylor term count (identical arithmetic on every CTA)
        const float z = 1.5f * fabsf(t) + 0.05f;
        int nterms;
        {
            float term = 1.f; int n = 0;
            while (n < MAX_TERMS) { n++; term *= z / (float)n; if (term < 1e-5f) break; }
            nterms = n;
        }

        // prefetch next gate's G tile into the other buffer
        if (tid == 0 && g + 1 < NGATES) {
            const int b = (g + 1) & 1;
            mbar_expect_tx(b ? mbG1 : mbG0, 65536u);
            bulk_g2s(sG_a + (unsigned)b * 65536u,
                     gens + (size_t)(g + 1) * DIM * DIM + (size_t)row0 * DIM,
                     65536u, b ? mbG1 : mbG0);
        }
        // wait for this gate's G tile
        {
            const int b = g & 1;
            mbar_wait(b ? mbG1 : mbG0, pGb[b]);
            pGb[b] ^= 1;
        }

        const float4* A4 = (const float4*)(sG + (size_t)(g & 1) * 16 * DIM + (size_t)la * DIM);
        const float4* B4 = A4 + DIM / 4;

        for (int n = 1; n <= nterms; n++) {
            // term 1 reads psi from sacc; later terms read staged w from sv
            const float4* vr = (n == 1) ? (const float4*)sacc : (const float4*)sv;
            const float4* vi = vr + DIM / 4;

            float dre_a = 0.f, dim_a = 0.f, dre_b = 0.f, dim_b = 0.f;
            #pragma unroll
            for (int k = 0; k < 8; k++) {
                const int idx = lane + 32 * k;
                const float4 va = vr[idx];
                const float4 vb = vi[idx];
                const float4 ga = A4[idx];
                const float4 gb = B4[idx];
                dre_a += ga.x*va.x + ga.y*va.y + ga.z*va.z + ga.w*va.w;
                dim_a += ga.x*vb.x + ga.y*vb.y + ga.z*vb.z + ga.w*vb.w;
                dre_b += gb.x*va.x + gb.y*va.y + gb.z*va.z + gb.w*va.w;
                dim_b += gb.x*vb.x + gb.y*vb.y + gb.z*vb.z + gb.w*vb.w;
            }
            #pragma unroll
            for (int o = 16; o; o >>= 1) {
                dre_a += __shfl_xor_sync(~0u, dre_a, o);
                dim_a += __shfl_xor_sync(~0u, dim_a, o);
                dre_b += __shfl_xor_sync(~0u, dre_b, o);
                dim_b += __shfl_xor_sync(~0u, dim_b, o);
            }
            const float sc = t / (float)n;   // w_n = (-i t/n)(G w_{n-1}): (-i)(a+bi)=b-ai

            if (g == NGATES - 1 && n == nterms) {
                // final term of final gate: everything needed is local — no exchange
                if (lane == 0) {
                    const float fre_a = sacc[r_a]       + sc * dim_a;
                    const float fim_a = sacc[DIM + r_a] - sc * dre_a;
                    const float fre_b = sacc[r_b]       + sc * dim_b;
                    const float fim_b = sacc[DIM + r_b] - sc * dre_b;
                    out[r_a] = fre_a * fre_a + fim_a * fim_a;
                    out[r_b] = fre_b * fre_b + fim_b * fim_b;
                }
                break;
            }

            // ---- exchange: publish my rows, central-counter barrier, gather ----
            if (lane == 0) {
                stg_cg_f2(&g_vec[slot][r_a],        sc * dim_a,  sc * dim_b);
                stg_cg_f2(&g_vec[slot][DIM + r_a], -sc * dre_a, -sc * dre_b);
                __threadfence();                    // data visible before my arrival
            }
            __syncthreads();

            it++;
            if (tid == 0) {
                red_add_release(&g_cnt, 1u);        // fire-and-forget arrival
                const unsigned target = base + 64u * it;
                unsigned v;
                do { v = ld_acquire(&g_cnt); } while ((int)(v - target) < 0);
            }
            __syncthreads();                        // broadcast barrier-passed

            // cooperative gather (L2) fused with psi accumulation
            const float4* gv = (const float4*)g_vec[slot];
            #pragma unroll
            for (int j = 0; j < 2; j++) {
                const int idx = tid + j * NTHREADS;
                const float4 w = __ldcg(&gv[idx]);
                ((float4*)sv)[idx] = w;
                float4 a = ((const float4*)sacc)[idx];
                a.x += w.x; a.y += w.y; a.z += w.z; a.w += w.w;
                ((float4*)sacc)[idx] = a;
            }
            __syncthreads();

            slot ^= 1;
        }
    }

    // advance epoch for the next launch/replay (single writer; safe: cta0 reaches
    // here only after the final barrier, i.e. all CTAs have arrived)
    if (cta == 0 && tid == 0) st_release(&g_base, base + 64u * it);
}

extern "C" void kernel_launch(void* const* d_in, const int* in_sizes, int n_in,
                              void* d_out, int out_size) {
    const float* feature = nullptr;
    const float* theta   = nullptr;
    const float* gens    = nullptr;
    for (int i = 0; i < n_in; i++) {
        if (in_sizes[i] == DIM)                     feature = (const float*)d_in[i];
        else if (in_sizes[i] == NGATES)             theta   = (const float*)d_in[i];
        else if (in_sizes[i] == NGATES * DIM * DIM) gens    = (const float*)d_in[i];
    }
    cudaFuncSetAttribute(qnn_kernel, cudaFuncAttributeMaxDynamicSharedMemorySize, SMEM_BYTES);
    qnn_kernel<<<NCTAS, NTHREADS, SMEM_BYTES>>>(feature, theta, gens, (float*)d_out);
}